// round 2
// baseline (speedup 1.0000x reference)
#include <cuda_runtime.h>
#include <cstdint>

// Problem constants
#define NB    32
#define LP    2048
#define LDRG  256
#define DD    512
#define GPNUM 512

typedef unsigned long long u64;

// packed f32x2 helpers (FFMA2 — ptxas never emits this from C++)
__device__ __forceinline__ u64 pack2(float x, float y) {
  u64 r; asm("mov.b64 %0,{%1,%2};" : "=l"(r) : "f"(x), "f"(y)); return r;
}
__device__ __forceinline__ void ffma2(u64& acc, u64 a, u64 b) {
  asm("fma.rn.f32x2 %0, %1, %2, %0;" : "+l"(acc) : "l"(a), "l"(b));
}
__device__ __forceinline__ float2 unpack2(u64 v) {
  float2 f; asm("mov.b64 {%0,%1}, %2;" : "=f"(f.x), "=f"(f.y) : "l"(v)); return f;
}

// ---------------- scratch ----------------
__device__ float g_scratch[79691776];
__device__ unsigned char g_masks[24576];
__device__ int g_flag;

// ---------------- mask handling ----------------
__device__ __forceinline__ bool read_mask(const void* p, int i, int f) {
  if (f == 0) return ((const unsigned char*)p)[i] != 0;
  if (f == 1) return ((const int*)p)[i] != 0;
  return ((const float*)p)[i] != 0.0f;
}

__global__ void detect_kernel(const unsigned char* __restrict__ p) {
  int big = 0, off = 0;
  for (int i = 0; i < 4096; ++i) {
    unsigned char c = p[i];
    big |= (c > 1) ? 1 : 0;
    off |= (c != 0 && (i & 3) != 0) ? 1 : 0;
  }
  g_flag = big ? 2 : (off ? 0 : 1);
}

__global__ void mask_kernel(const void* __restrict__ mp, const void* __restrict__ md,
                            float* __restrict__ outMP, float* __restrict__ outMD) {
  int f = g_flag;
  int idx = blockIdx.x * blockDim.x + threadIdx.x;
  if (idx < NB * GPNUM) {
    int b = idx / GPNUM, g = idx % GPNUM;
    int base = b * LP + g * 4;
    bool any = false;
#pragma unroll
    for (int r = 0; r < 4; ++r) any = any || read_mask(mp, base + r, f);
    g_masks[idx] = any ? 1 : 0;
    outMP[idx] = any ? 1.0f : 0.0f;
  } else {
    int j = idx - NB * GPNUM;
    if (j < NB * LDRG) {
      bool v = read_mask(md, j, f);
      g_masks[16384 + j] = v ? 1 : 0;
      outMD[j] = v ? 1.0f : 0.0f;
    }
  }
}

// ---------------- grouping ----------------
__global__ void group_kernel(const float* __restrict__ P, float* __restrict__ G) {
  int idx = blockIdx.x * 256 + threadIdx.x;
  int d = idx & 511;
  int g = (idx >> 9) & 511;
  int b = idx >> 18;
  const float* p = P + ((size_t)b * LP + (size_t)g * 4) * DD + d;
  G[idx] = 0.25f * (p[0] + p[512] + p[1024] + p[1536]);
}

// ============ projection GEMM: C[M,512] = A[M,512] @ W[512,512]^T ============
// 128x128x16 tile, 256 threads, 8x8 micro-tile via FFMA2
__global__ __launch_bounds__(256) void gemm_proj(
    const float* __restrict__ A, const float* __restrict__ W, float* __restrict__ C) {
  __shared__ __align__(16) float As[16][132];
  __shared__ __align__(16) float Bs[16][132];
  const int tid = threadIdx.x;
  const int tx = tid & 15, ty = tid >> 4;
  const int mBase = blockIdx.x * 128;
  const int nBase = blockIdx.y * 128;

  u64 acc[8][4];
#pragma unroll
  for (int i = 0; i < 8; ++i)
#pragma unroll
    for (int j = 0; j < 4; ++j) acc[i][j] = 0ULL;

  for (int k0 = 0; k0 < 512; k0 += 16) {
#pragma unroll
    for (int i = tid; i < 512; i += 256) {
      int r = i >> 2, c = (i & 3) * 4;
      float4 v = *(const float4*)(A + (size_t)(mBase + r) * 512 + k0 + c);
      As[c][r] = v.x; As[c + 1][r] = v.y; As[c + 2][r] = v.z; As[c + 3][r] = v.w;
    }
#pragma unroll
    for (int i = tid; i < 512; i += 256) {
      int r = i >> 2, c = (i & 3) * 4;
      float4 v = *(const float4*)(W + (size_t)(nBase + r) * 512 + k0 + c);
      Bs[c][r] = v.x; Bs[c + 1][r] = v.y; Bs[c + 2][r] = v.z; Bs[c + 3][r] = v.w;
    }
    __syncthreads();
#pragma unroll
    for (int kk = 0; kk < 16; ++kk) {
      float4 a0 = *(const float4*)&As[kk][ty * 8];
      float4 a1 = *(const float4*)&As[kk][ty * 8 + 4];
      float4 b0 = *(const float4*)&Bs[kk][tx * 8];
      float4 b1 = *(const float4*)&Bs[kk][tx * 8 + 4];
      u64 bp[4] = {pack2(b0.x, b0.y), pack2(b0.z, b0.w),
                   pack2(b1.x, b1.y), pack2(b1.z, b1.w)};
      float av[8] = {a0.x, a0.y, a0.z, a0.w, a1.x, a1.y, a1.z, a1.w};
#pragma unroll
      for (int i = 0; i < 8; ++i) {
        u64 ad = pack2(av[i], av[i]);
#pragma unroll
        for (int j = 0; j < 4; ++j) ffma2(acc[i][j], ad, bp[j]);
      }
    }
    __syncthreads();
  }
#pragma unroll
  for (int i = 0; i < 8; ++i) {
    float2 f0 = unpack2(acc[i][0]), f1 = unpack2(acc[i][1]);
    float2 f2 = unpack2(acc[i][2]), f3 = unpack2(acc[i][3]);
    float* cp = C + (size_t)(mBase + ty * 8 + i) * 512 + nBase + tx * 8;
    *(float4*)cp = make_float4(f0.x, f0.y, f1.x, f1.y);
    *(float4*)(cp + 4) = make_float4(f2.x, f2.y, f3.x, f3.y);
  }
}

// ============ logits GEMM: S[b,h,l,k] = Q.Kt over dh=64, masked ============
// 128x128x16 tile, 256 threads
__global__ __launch_bounds__(256) void gemm_logits(
    const float* __restrict__ Q, const float* __restrict__ Km, float* __restrict__ S,
    const unsigned char* __restrict__ mq, const unsigned char* __restrict__ mk,
    int Lq, int Lk) {
  __shared__ __align__(16) float As[16][132];
  __shared__ __align__(16) float Bs[16][132];
  const int tid = threadIdx.x;
  const int tx = tid & 15, ty = tid >> 4;
  const int mBase = blockIdx.x * 128;
  const int nBase = blockIdx.y * 128;
  const int z = blockIdx.z;
  const int b = z >> 3, h = z & 7;
  const float* A = Q + (size_t)b * Lq * 512 + h * 64;
  const float* B = Km + (size_t)b * Lk * 512 + h * 64;
  float* C = S + (size_t)z * Lq * Lk;
  const unsigned char* mqb = mq + b * Lq;
  const unsigned char* mkb = mk + b * Lk;

  u64 acc[8][4];
#pragma unroll
  for (int i = 0; i < 8; ++i)
#pragma unroll
    for (int j = 0; j < 4; ++j) acc[i][j] = 0ULL;

  for (int k0 = 0; k0 < 64; k0 += 16) {
#pragma unroll
    for (int i = tid; i < 512; i += 256) {
      int r = i >> 2, c = (i & 3) * 4;
      float4 v = *(const float4*)(A + (size_t)(mBase + r) * 512 + k0 + c);
      As[c][r] = v.x; As[c + 1][r] = v.y; As[c + 2][r] = v.z; As[c + 3][r] = v.w;
    }
#pragma unroll
    for (int i = tid; i < 512; i += 256) {
      int r = i >> 2, c = (i & 3) * 4;
      float4 v = *(const float4*)(B + (size_t)(nBase + r) * 512 + k0 + c);
      Bs[c][r] = v.x; Bs[c + 1][r] = v.y; Bs[c + 2][r] = v.z; Bs[c + 3][r] = v.w;
    }
    __syncthreads();
#pragma unroll
    for (int kk = 0; kk < 16; ++kk) {
      float4 a0 = *(const float4*)&As[kk][ty * 8];
      float4 a1 = *(const float4*)&As[kk][ty * 8 + 4];
      float4 b0 = *(const float4*)&Bs[kk][tx * 8];
      float4 b1 = *(const float4*)&Bs[kk][tx * 8 + 4];
      u64 bp[4] = {pack2(b0.x, b0.y), pack2(b0.z, b0.w),
                   pack2(b1.x, b1.y), pack2(b1.z, b1.w)};
      float av[8] = {a0.x, a0.y, a0.z, a0.w, a1.x, a1.y, a1.z, a1.w};
#pragma unroll
      for (int i = 0; i < 8; ++i) {
        u64 ad = pack2(av[i], av[i]);
#pragma unroll
        for (int j = 0; j < 4; ++j) ffma2(acc[i][j], ad, bp[j]);
      }
    }
    __syncthreads();
  }
  unsigned char rm[8], cm[8];
#pragma unroll
  for (int i = 0; i < 8; ++i) rm[i] = mqb[mBase + ty * 8 + i];
#pragma unroll
  for (int j = 0; j < 8; ++j) cm[j] = mkb[nBase + tx * 8 + j];
#pragma unroll
  for (int i = 0; i < 8; ++i) {
    float2 f[4] = {unpack2(acc[i][0]), unpack2(acc[i][1]),
                   unpack2(acc[i][2]), unpack2(acc[i][3])};
    float vals[8] = {f[0].x, f[0].y, f[1].x, f[1].y, f[2].x, f[2].y, f[3].x, f[3].y};
#pragma unroll
    for (int j = 0; j < 8; ++j)
      vals[j] -= (rm[i] && cm[j]) ? 0.0f : 1.0e6f;
    float* cp = C + (size_t)(mBase + ty * 8 + i) * Lk + nBase + tx * 8;
    *(float4*)cp = make_float4(vals[0], vals[1], vals[2], vals[3]);
    *(float4*)(cp + 4) = make_float4(vals[4], vals[5], vals[6], vals[7]);
  }
}

// ============ AV GEMM: Out[b,l,h*64+n] = sum_k Alpha[b,h,l,k] V[b,k,h*64+n] ====
// 128x64x16 tile, 128 threads
__global__ __launch_bounds__(128) void gemm_av(
    const float* __restrict__ Alp, const float* __restrict__ V, float* __restrict__ Out,
    int Lq, int Lk) {
  __shared__ __align__(16) float As[16][132];
  __shared__ __align__(16) float Bs[16][68];
  const int tid = threadIdx.x;
  const int tx = tid & 7, ty = tid >> 3;
  const int mBase = blockIdx.x * 128;
  const int z = blockIdx.z;
  const int b = z >> 3, h = z & 7;
  const float* A = Alp + (size_t)z * Lq * Lk;
  const float* B = V + (size_t)b * Lk * 512 + h * 64;
  float* C = Out + (size_t)b * Lq * 512 + h * 64;

  u64 acc[8][4];
#pragma unroll
  for (int i = 0; i < 8; ++i)
#pragma unroll
    for (int j = 0; j < 4; ++j) acc[i][j] = 0ULL;

  for (int k0 = 0; k0 < Lk; k0 += 16) {
#pragma unroll
    for (int i = tid; i < 512; i += 128) {
      int r = i >> 2, c = (i & 3) * 4;
      float4 v = *(const float4*)(A + (size_t)(mBase + r) * Lk + k0 + c);
      As[c][r] = v.x; As[c + 1][r] = v.y; As[c + 2][r] = v.z; As[c + 3][r] = v.w;
    }
#pragma unroll
    for (int i = tid; i < 256; i += 128) {
      int r = i >> 4, c = (i & 15) * 4;
      float4 v = *(const float4*)(B + (size_t)(k0 + r) * 512 + c);
      *(float4*)&Bs[r][c] = v;
    }
    __syncthreads();
#pragma unroll
    for (int kk = 0; kk < 16; ++kk) {
      float4 a0 = *(const float4*)&As[kk][ty * 8];
      float4 a1 = *(const float4*)&As[kk][ty * 8 + 4];
      float4 b0 = *(const float4*)&Bs[kk][tx * 8];
      float4 b1 = *(const float4*)&Bs[kk][tx * 8 + 4];
      u64 bp[4] = {pack2(b0.x, b0.y), pack2(b0.z, b0.w),
                   pack2(b1.x, b1.y), pack2(b1.z, b1.w)};
      float av[8] = {a0.x, a0.y, a0.z, a0.w, a1.x, a1.y, a1.z, a1.w};
#pragma unroll
      for (int i = 0; i < 8; ++i) {
        u64 ad = pack2(av[i], av[i]);
#pragma unroll
        for (int j = 0; j < 4; ++j) ffma2(acc[i][j], ad, bp[j]);
      }
    }
    __syncthreads();
  }
#pragma unroll
  for (int i = 0; i < 8; ++i) {
    float2 f0 = unpack2(acc[i][0]), f1 = unpack2(acc[i][1]);
    float2 f2 = unpack2(acc[i][2]), f3 = unpack2(acc[i][3]);
    float* cp = C + (size_t)(mBase + ty * 8 + i) * 512 + tx * 8;
    *(float4*)cp = make_float4(f0.x, f0.y, f1.x, f1.y);
    *(float4*)(cp + 4) = make_float4(f2.x, f2.y, f3.x, f3.y);
  }
}

// ---------------- softmax ----------------
template <int LK>
__global__ __launch_bounds__(256) void softmax_kernel(
    float* __restrict__ S, const unsigned char* __restrict__ mq,
    float* __restrict__ alphaOut, int Lq) {
  __shared__ float sb[8][LK + 1];
  const int l = blockIdx.x, b = blockIdx.y;
  const int tid = threadIdx.x, w = tid >> 5, lane = tid & 31;
  const size_t abase = ((size_t)b * Lq + l) * (size_t)(LK * 8);

  if (!mq[b * Lq + l]) {
    for (int idx = tid; idx < LK * 8; idx += 256) alphaOut[abase + idx] = 0.0f;
#pragma unroll
    for (int h = 0; h < 8; ++h) {
      float* srow = S + ((size_t)(b * 8 + h) * Lq + l) * LK;
      for (int k = tid; k < LK; k += 256) srow[k] = 0.0f;
    }
    return;
  }

  float* srow = S + ((size_t)(b * 8 + w) * Lq + l) * LK;
  const int nit = LK / 32;
  float v[LK / 32];
  float mx = -3.0e38f;
#pragma unroll
  for (int i = 0; i < nit; ++i) { v[i] = srow[lane + 32 * i]; mx = fmaxf(mx, v[i]); }
#pragma unroll
  for (int o = 16; o > 0; o >>= 1) mx = fmaxf(mx, __shfl_xor_sync(0xffffffffu, mx, o));
  float sum = 0.0f;
#pragma unroll
  for (int i = 0; i < nit; ++i) { float e = expf(v[i] - mx); v[i] = e; sum += e; }
#pragma unroll
  for (int o = 16; o > 0; o >>= 1) sum += __shfl_xor_sync(0xffffffffu, sum, o);
  float inv = 1.0f / sum;
#pragma unroll
  for (int i = 0; i < nit; ++i) {
    float a = v[i] * inv;
    srow[lane + 32 * i] = a;
    sb[w][lane + 32 * i] = a;
  }
  __syncthreads();
#pragma unroll 4
  for (int idx = tid; idx < LK * 8; idx += 256) {
    int k = idx >> 3, h = idx & 7;
    alphaOut[abase + idx] = sb[h][k];
  }
}

// ---------------- launch ----------------
extern "C" void kernel_launch(void* const* d_in, const int* in_sizes, int n_in,
                              void* d_out, int out_size) {
  const float* protein = (const float*)d_in[0];
  const float* drug    = (const float*)d_in[1];
  const void*  mpraw   = d_in[2];
  const void*  mdraw   = d_in[3];
  const float* Wqp = (const float*)d_in[4];
  const float* Wkp = (const float*)d_in[5];
  const float* Wvp = (const float*)d_in[6];
  const float* Wqd = (const float*)d_in[7];
  const float* Wkd = (const float*)d_in[8];
  const float* Wvd = (const float*)d_in[9];
  float* out = (float*)d_out;

  float* sc = nullptr;
  cudaGetSymbolAddress((void**)&sc, g_scratch);
  unsigned char* mg = nullptr;
  cudaGetSymbolAddress((void**)&mg, g_masks);

  float* protg = sc;
  float* QP = sc + 8388608;
  float* KP = sc + 16777216;
  float* VP = sc + 25165824;
  float* QD = sc + 33554432;
  float* KD = sc + 37748736;
  float* VD = sc + 41943040;
  float* Sb = sc + 46137344;
  unsigned char* mpg = mg;
  unsigned char* mdg = mg + 16384;

  const size_t OFF_PROT = 0;
  const size_t OFF_DRUG = 8388608;
  const size_t OFF_MP   = 12582912;
  const size_t OFF_MD   = 12599296;
  const size_t OFF_APD  = 12607488;
  const size_t OFF_ADP  = 46161920;

  detect_kernel<<<1, 1>>>((const unsigned char*)mpraw);
  mask_kernel<<<96, 256>>>(mpraw, mdraw, out + OFF_MP, out + OFF_MD);
  group_kernel<<<32768, 256>>>(protein, protg);

  gemm_proj<<<dim3(128, 4), 256>>>(protg, Wqp, QP);
  gemm_proj<<<dim3(128, 4), 256>>>(protg, Wkp, KP);
  gemm_proj<<<dim3(128, 4), 256>>>(protg, Wvp, VP);
  gemm_proj<<<dim3(64, 4), 256>>>(drug, Wqd, QD);
  gemm_proj<<<dim3(64, 4), 256>>>(drug, Wkd, KD);
  gemm_proj<<<dim3(64, 4), 256>>>(drug, Wvd, VD);

  // protein->drug: Lq=512, Lk=256
  gemm_logits<<<dim3(4, 2, 256), 256>>>(QP, KD, Sb, mpg, mdg, 512, 256);
  softmax_kernel<256><<<dim3(512, 32), 256>>>(Sb, mpg, out + OFF_APD, 512);
  gemm_av<<<dim3(4, 1, 256), 128>>>(Sb, VD, out + OFF_PROT, 512, 256);

  // drug->protein: Lq=256, Lk=512
  gemm_logits<<<dim3(2, 4, 256), 256>>>(QD, KP, Sb, mdg, mpg, 256, 512);
  softmax_kernel<512><<<dim3(256, 32), 256>>>(Sb, mdg, out + OFF_ADP, 256);
  gemm_av<<<dim3(2, 1, 256), 128>>>(Sb, VP, out + OFF_DRUG, 256, 512);

  (void)in_sizes; (void)n_in; (void)out_size;
}

// round 4
// speedup vs baseline: 1.4352x; 1.4352x over previous
#include <cuda_runtime.h>
#include <cuda_bf16.h>
#include <cstdint>

#define NB    32
#define LP    2048
#define LDRG  256
#define DD    512
#define GPNUM 512

// ======================= scratch =======================
//  QP 0  KP 8388608  VP 16777216
//  QD 25165824  KD 29360128  VD 33554432
//  S  37748736 (33554432)
//  PGH 71303168  PGL 75497472   (protein-group bf16 hi/lo, 8M elem each -> 4M floats)
//  DRH 79691776  DRL 81788928   (drug bf16 hi/lo)
//  WH  83886080  WL 84672512    (weights bf16 hi/lo, 6*262144 elems each)
__device__ float g_scratch[85458944];
__device__ unsigned char g_masks[24576];
__device__ int g_flag;

// ======================= masks =======================
__device__ __forceinline__ bool read_mask(const void* p, int i, int f) {
  if (f == 0) return ((const unsigned char*)p)[i] != 0;
  if (f == 1) return ((const int*)p)[i] != 0;
  return ((const float*)p)[i] != 0.0f;
}
__global__ void detect_kernel(const unsigned char* __restrict__ p) {
  int big = 0, off = 0;
  for (int i = 0; i < 4096; ++i) {
    unsigned char c = p[i];
    big |= (c > 1) ? 1 : 0;
    off |= (c != 0 && (i & 3) != 0) ? 1 : 0;
  }
  g_flag = big ? 2 : (off ? 0 : 1);
}
__global__ void mask_kernel(const void* __restrict__ mp, const void* __restrict__ md,
                            float* __restrict__ outMP, float* __restrict__ outMD) {
  int f = g_flag;
  int idx = blockIdx.x * blockDim.x + threadIdx.x;
  if (idx < NB * GPNUM) {
    int b = idx / GPNUM, g = idx % GPNUM;
    int base = b * LP + g * 4;
    bool any = false;
#pragma unroll
    for (int r = 0; r < 4; ++r) any = any || read_mask(mp, base + r, f);
    g_masks[idx] = any ? 1 : 0;
    outMP[idx] = any ? 1.0f : 0.0f;
  } else {
    int j = idx - NB * GPNUM;
    if (j < NB * LDRG) {
      bool v = read_mask(md, j, f);
      g_masks[16384 + j] = v ? 1 : 0;
      outMD[j] = v ? 1.0f : 0.0f;
    }
  }
}

// ============== grouping + bf16 hi/lo split ==============
__global__ void group_bf16_kernel(const float* __restrict__ P,
                                  __nv_bfloat16* __restrict__ H,
                                  __nv_bfloat16* __restrict__ L) {
  int idx = blockIdx.x * 256 + threadIdx.x;
  int d = idx & 511;
  int g = (idx >> 9) & 511;
  int b = idx >> 18;
  const float* p = P + ((size_t)b * LP + (size_t)g * 4) * DD + d;
  float x = 0.25f * (p[0] + p[512] + p[1024] + p[1536]);
  __nv_bfloat16 h = __float2bfloat16_rn(x);
  H[idx] = h;
  L[idx] = __float2bfloat16_rn(x - __bfloat162float(h));
}

__global__ void cvt_bf16_kernel(const float* __restrict__ X, int n,
                                __nv_bfloat16* __restrict__ H,
                                __nv_bfloat16* __restrict__ L) {
  int i = blockIdx.x * 256 + threadIdx.x;
  if (i >= n) return;
  float x = X[i];
  __nv_bfloat16 h = __float2bfloat16_rn(x);
  H[i] = h;
  L[i] = __float2bfloat16_rn(x - __bfloat162float(h));
}

// ====== mma.sync bf16x3 projection: C[M,512] = A[M,512] @ W[512,512]^T ======
// block 128(M) x 64(N), BK=32, 256 threads = 8 warps, warp tile 32x32.
#define MMA_BF16(c, a, b)                                                      \
  asm volatile("mma.sync.aligned.m16n8k16.row.col.f32.bf16.bf16.f32 "          \
               "{%0,%1,%2,%3}, {%4,%5,%6,%7}, {%8,%9}, {%0,%1,%2,%3};"         \
               : "+f"((c)[0]), "+f"((c)[1]), "+f"((c)[2]), "+f"((c)[3])        \
               : "r"((a)[0]), "r"((a)[1]), "r"((a)[2]), "r"((a)[3]),           \
                 "r"((b)[0]), "r"((b)[1]))

__global__ __launch_bounds__(256) void gemm_proj_mma(
    const __nv_bfloat16* __restrict__ Ah, const __nv_bfloat16* __restrict__ Al,
    const __nv_bfloat16* __restrict__ Wh, const __nv_bfloat16* __restrict__ Wl,
    float* __restrict__ C) {
  __shared__ __align__(16) __nv_bfloat16 Ahs[128][40];
  __shared__ __align__(16) __nv_bfloat16 Als[128][40];
  __shared__ __align__(16) __nv_bfloat16 Bhs[64][40];
  __shared__ __align__(16) __nv_bfloat16 Bls[64][40];

  const int tid = threadIdx.x;
  const int w = tid >> 5, lane = tid & 31;
  const int g = lane >> 2, t4 = lane & 3;
  const int wm = (w >> 1) * 32, wn = (w & 1) * 32;
  const int mBase = blockIdx.x * 128;
  const int nBase = blockIdx.y * 64;

  float acc[2][4][4];
#pragma unroll
  for (int mi = 0; mi < 2; ++mi)
#pragma unroll
    for (int j = 0; j < 4; ++j)
#pragma unroll
      for (int q = 0; q < 4; ++q) acc[mi][j][q] = 0.0f;

  for (int k0 = 0; k0 < 512; k0 += 32) {
    // A tiles: 128 rows x 32 bf16 (hi & lo)
#pragma unroll
    for (int u = tid; u < 512; u += 256) {
      int row = u >> 2, seg = u & 3;
      size_t ga = (size_t)(mBase + row) * 512 + k0 + seg * 8;
      *(uint4*)&Ahs[row][seg * 8] = *(const uint4*)(Ah + ga);
      *(uint4*)&Als[row][seg * 8] = *(const uint4*)(Al + ga);
    }
    // B tiles: 64 rows x 32 bf16 (hi & lo)
    {
      int u = tid;
      if (u < 256) {
        int row = u >> 2, seg = u & 3;
        size_t ga = (size_t)(nBase + row) * 512 + k0 + seg * 8;
        *(uint4*)&Bhs[row][seg * 8] = *(const uint4*)(Wh + ga);
        *(uint4*)&Bls[row][seg * 8] = *(const uint4*)(Wl + ga);
      }
    }
    __syncthreads();

#pragma unroll
    for (int kk = 0; kk < 32; kk += 16) {
      const int kb = kk + t4 * 2;
      uint32_t ah[2][4], al[2][4];
#pragma unroll
      for (int mi = 0; mi < 2; ++mi) {
        int r0 = wm + mi * 16 + g, r1 = r0 + 8;
        ah[mi][0] = *(const uint32_t*)&Ahs[r0][kb];
        ah[mi][1] = *(const uint32_t*)&Ahs[r1][kb];
        ah[mi][2] = *(const uint32_t*)&Ahs[r0][kb + 8];
        ah[mi][3] = *(const uint32_t*)&Ahs[r1][kb + 8];
        al[mi][0] = *(const uint32_t*)&Als[r0][kb];
        al[mi][1] = *(const uint32_t*)&Als[r1][kb];
        al[mi][2] = *(const uint32_t*)&Als[r0][kb + 8];
        al[mi][3] = *(const uint32_t*)&Als[r1][kb + 8];
      }
      uint32_t bh[4][2], bl[4][2];
#pragma unroll
      for (int j = 0; j < 4; ++j) {
        int n = wn + j * 8 + g;
        bh[j][0] = *(const uint32_t*)&Bhs[n][kb];
        bh[j][1] = *(const uint32_t*)&Bhs[n][kb + 8];
        bl[j][0] = *(const uint32_t*)&Bls[n][kb];
        bl[j][1] = *(const uint32_t*)&Bls[n][kb + 8];
      }
#pragma unroll
      for (int mi = 0; mi < 2; ++mi)
#pragma unroll
        for (int j = 0; j < 4; ++j) {
          MMA_BF16(acc[mi][j], ah[mi], bh[j]);
          MMA_BF16(acc[mi][j], ah[mi], bl[j]);
          MMA_BF16(acc[mi][j], al[mi], bh[j]);
        }
    }
    __syncthreads();
  }

#pragma unroll
  for (int mi = 0; mi < 2; ++mi) {
    int row = mBase + wm + mi * 16 + g;
#pragma unroll
    for (int j = 0; j < 4; ++j) {
      int col = nBase + wn + j * 8 + t4 * 2;
      *(float2*)(C + (size_t)row * 512 + col) = make_float2(acc[mi][j][0], acc[mi][j][1]);
      *(float2*)(C + (size_t)(row + 8) * 512 + col) = make_float2(acc[mi][j][2], acc[mi][j][3]);
    }
  }
}

// ============ attention GEMMs (R1 proven fp32-FMA versions) ============
#define BM 128
#define BN 64
#define BK 16

__global__ __launch_bounds__(128) void gemm_logits(
    const float* __restrict__ Q, const float* __restrict__ Km, float* __restrict__ S,
    const unsigned char* __restrict__ mq, const unsigned char* __restrict__ mk,
    int Lq, int Lk) {
  __shared__ __align__(16) float As[BK][BM + 4];
  __shared__ __align__(16) float Bs[BK][BN + 4];
  const int tid = threadIdx.x;
  const int tx = tid & 7, ty = tid >> 3;
  const int mBase = blockIdx.x * BM;
  const int nBase = blockIdx.y * BN;
  const int z = blockIdx.z;
  const int b = z >> 3, h = z & 7;
  const float* A = Q + (size_t)b * Lq * 512 + h * 64;
  const float* B = Km + (size_t)b * Lk * 512 + h * 64;
  float* C = S + (size_t)z * Lq * Lk;
  const unsigned char* mqb = mq + b * Lq;
  const unsigned char* mkb = mk + b * Lk;

  float acc[8][8];
#pragma unroll
  for (int i = 0; i < 8; ++i)
#pragma unroll
    for (int j = 0; j < 8; ++j) acc[i][j] = 0.0f;

  for (int k0 = 0; k0 < 64; k0 += BK) {
#pragma unroll
    for (int i = tid * 4; i < BM * BK; i += 512) {
      int r = i >> 4, c = i & 15;
      float4 v = *(const float4*)(A + (size_t)(mBase + r) * 512 + k0 + c);
      As[c][r] = v.x; As[c + 1][r] = v.y; As[c + 2][r] = v.z; As[c + 3][r] = v.w;
    }
#pragma unroll
    for (int i = tid * 4; i < BN * BK; i += 512) {
      int r = i >> 4, c = i & 15;
      float4 v = *(const float4*)(B + (size_t)(nBase + r) * 512 + k0 + c);
      Bs[c][r] = v.x; Bs[c + 1][r] = v.y; Bs[c + 2][r] = v.z; Bs[c + 3][r] = v.w;
    }
    __syncthreads();
#pragma unroll
    for (int kk = 0; kk < BK; ++kk) {
      float4 a0 = *(const float4*)&As[kk][ty * 8];
      float4 a1 = *(const float4*)&As[kk][ty * 8 + 4];
      float4 b0 = *(const float4*)&Bs[kk][tx * 8];
      float4 b1 = *(const float4*)&Bs[kk][tx * 8 + 4];
      float a[8] = {a0.x, a0.y, a0.z, a0.w, a1.x, a1.y, a1.z, a1.w};
      float bb[8] = {b0.x, b0.y, b0.z, b0.w, b1.x, b1.y, b1.z, b1.w};
#pragma unroll
      for (int i = 0; i < 8; ++i)
#pragma unroll
        for (int j = 0; j < 8; ++j) acc[i][j] += a[i] * bb[j];
    }
    __syncthreads();
  }
  unsigned char rm[8], cm[8];
#pragma unroll
  for (int i = 0; i < 8; ++i) rm[i] = mqb[mBase + ty * 8 + i];
#pragma unroll
  for (int j = 0; j < 8; ++j) cm[j] = mkb[nBase + tx * 8 + j];
#pragma unroll
  for (int i = 0; i < 8; ++i) {
    float vals[8];
#pragma unroll
    for (int j = 0; j < 8; ++j)
      vals[j] = acc[i][j] - ((rm[i] && cm[j]) ? 0.0f : 1.0e6f);
    float* cp = C + (size_t)(mBase + ty * 8 + i) * Lk + nBase + tx * 8;
    *(float4*)cp = make_float4(vals[0], vals[1], vals[2], vals[3]);
    *(float4*)(cp + 4) = make_float4(vals[4], vals[5], vals[6], vals[7]);
  }
}

__global__ __launch_bounds__(128) void gemm_av(
    const float* __restrict__ Alp, const float* __restrict__ V, float* __restrict__ Out,
    int Lq, int Lk) {
  __shared__ __align__(16) float As[BK][BM + 4];
  __shared__ __align__(16) float Bs[BK][BN + 4];
  const int tid = threadIdx.x;
  const int tx = tid & 7, ty = tid >> 3;
  const int mBase = blockIdx.x * BM;
  const int z = blockIdx.z;
  const int b = z >> 3, h = z & 7;
  const float* A = Alp + (size_t)z * Lq * Lk;
  const float* B = V + (size_t)b * Lk * 512 + h * 64;
  float* C = Out + (size_t)b * Lq * 512 + h * 64;

  float acc[8][8];
#pragma unroll
  for (int i = 0; i < 8; ++i)
#pragma unroll
    for (int j = 0; j < 8; ++j) acc[i][j] = 0.0f;

  for (int k0 = 0; k0 < Lk; k0 += BK) {
#pragma unroll
    for (int i = tid * 4; i < BM * BK; i += 512) {
      int r = i >> 4, c = i & 15;
      float4 v = *(const float4*)(A + (size_t)(mBase + r) * Lk + k0 + c);
      As[c][r] = v.x; As[c + 1][r] = v.y; As[c + 2][r] = v.z; As[c + 3][r] = v.w;
    }
#pragma unroll
    for (int i = tid * 4; i < BK * BN; i += 512) {
      int r = i >> 6, c = i & 63;
      float4 v = *(const float4*)(B + (size_t)(k0 + r) * 512 + c);
      *(float4*)&Bs[r][c] = v;
    }
    __syncthreads();
#pragma unroll
    for (int kk = 0; kk < BK; ++kk) {
      float4 a0 = *(const float4*)&As[kk][ty * 8];
      float4 a1 = *(const float4*)&As[kk][ty * 8 + 4];
      float4 b0 = *(const float4*)&Bs[kk][tx * 8];
      float4 b1 = *(const float4*)&Bs[kk][tx * 8 + 4];
      float a[8] = {a0.x, a0.y, a0.z, a0.w, a1.x, a1.y, a1.z, a1.w};
      float bb[8] = {b0.x, b0.y, b0.z, b0.w, b1.x, b1.y, b1.z, b1.w};
#pragma unroll
      for (int i = 0; i < 8; ++i)
#pragma unroll
        for (int j = 0; j < 8; ++j) acc[i][j] += a[i] * bb[j];
    }
    __syncthreads();
  }
#pragma unroll
  for (int i = 0; i < 8; ++i) {
    float* cp = C + (size_t)(mBase + ty * 8 + i) * 512 + tx * 8;
    *(float4*)cp = make_float4(acc[i][0], acc[i][1], acc[i][2], acc[i][3]);
    *(float4*)(cp + 4) = make_float4(acc[i][4], acc[i][5], acc[i][6], acc[i][7]);
  }
}

// ---------------- softmax ----------------
template <int LK>
__global__ __launch_bounds__(256) void softmax_kernel(
    float* __restrict__ S, const unsigned char* __restrict__ mq,
    float* __restrict__ alphaOut, int Lq) {
  __shared__ float sbuf[8][LK + 1];
  const int l = blockIdx.x, b = blockIdx.y;
  const int tid = threadIdx.x, w = tid >> 5, lane = tid & 31;
  const size_t abase = ((size_t)b * Lq + l) * (size_t)(LK * 8);

  if (!mq[b * Lq + l]) {
    for (int idx = tid; idx < LK * 8; idx += 256) alphaOut[abase + idx] = 0.0f;
#pragma unroll
    for (int h = 0; h < 8; ++h) {
      float* srow = S + ((size_t)(b * 8 + h) * Lq + l) * LK;
      for (int k = tid; k < LK; k += 256) srow[k] = 0.0f;
    }
    return;
  }

  float* srow = S + ((size_t)(b * 8 + w) * Lq + l) * LK;
  const int nit = LK / 32;
  float v[LK / 32];
  float mx = -3.0e38f;
#pragma unroll
  for (int i = 0; i < nit; ++i) { v[i] = srow[lane + 32 * i]; mx = fmaxf(mx, v[i]); }
#pragma unroll
  for (int o = 16; o > 0; o >>= 1) mx = fmaxf(mx, __shfl_xor_sync(0xffffffffu, mx, o));
  float sum = 0.0f;
#pragma unroll
  for (int i = 0; i < nit; ++i) { float e = expf(v[i] - mx); v[i] = e; sum += e; }
#pragma unroll
  for (int o = 16; o > 0; o >>= 1) sum += __shfl_xor_sync(0xffffffffu, sum, o);
  float inv = 1.0f / sum;
#pragma unroll
  for (int i = 0; i < nit; ++i) {
    float a = v[i] * inv;
    srow[lane + 32 * i] = a;
    sbuf[w][lane + 32 * i] = a;
  }
  __syncthreads();
#pragma unroll 4
  for (int idx = tid; idx < LK * 8; idx += 256) {
    int k = idx >> 3, h = idx & 7;
    alphaOut[abase + idx] = sbuf[h][k];
  }
}

// ---------------- launch ----------------
extern "C" void kernel_launch(void* const* d_in, const int* in_sizes, int n_in,
                              void* d_out, int out_size) {
  const float* protein = (const float*)d_in[0];
  const float* drug    = (const float*)d_in[1];
  const void*  mpraw   = d_in[2];
  const void*  mdraw   = d_in[3];
  const float* W[6] = {(const float*)d_in[4], (const float*)d_in[5], (const float*)d_in[6],
                       (const float*)d_in[7], (const float*)d_in[8], (const float*)d_in[9]};
  float* out = (float*)d_out;

  float* sc = nullptr;
  cudaGetSymbolAddress((void**)&sc, g_scratch);
  unsigned char* mg = nullptr;
  cudaGetSymbolAddress((void**)&mg, g_masks);

  float* QP = sc;
  float* KP = sc + 8388608;
  float* VP = sc + 16777216;
  float* QD = sc + 25165824;
  float* KD = sc + 29360128;
  float* VD = sc + 33554432;
  float* Sb = sc + 37748736;
  __nv_bfloat16* PGH = (__nv_bfloat16*)(sc + 71303168);
  __nv_bfloat16* PGL = (__nv_bfloat16*)(sc + 75497472);
  __nv_bfloat16* DRH = (__nv_bfloat16*)(sc + 79691776);
  __nv_bfloat16* DRL = (__nv_bfloat16*)(sc + 81788928);
  __nv_bfloat16* WHb = (__nv_bfloat16*)(sc + 83886080);
  __nv_bfloat16* WLb = (__nv_bfloat16*)(sc + 84672512);
  unsigned char* mpg = mg;
  unsigned char* mdg = mg + 16384;

  const size_t OFF_PROT = 0;
  const size_t OFF_DRUG = 8388608;
  const size_t OFF_MP   = 12582912;
  const size_t OFF_MD   = 12599296;
  const size_t OFF_APD  = 12607488;
  const size_t OFF_ADP  = 46161920;

  detect_kernel<<<1, 1>>>((const unsigned char*)mpraw);
  mask_kernel<<<96, 256>>>(mpraw, mdraw, out + OFF_MP, out + OFF_MD);
  group_bf16_kernel<<<32768, 256>>>(protein, PGH, PGL);
  cvt_bf16_kernel<<<16384, 256>>>(drug, 4194304, DRH, DRL);
  for (int i = 0; i < 6; ++i)
    cvt_bf16_kernel<<<1024, 256>>>(W[i], 262144, WHb + (size_t)i * 262144,
                                   WLb + (size_t)i * 262144);

  // projections via mma.sync bf16x3
  float* outsP[3] = {QP, KP, VP};
  for (int i = 0; i < 3; ++i)
    gemm_proj_mma<<<dim3(128, 8), 256>>>(PGH, PGL, WHb + (size_t)i * 262144,
                                         WLb + (size_t)i * 262144, outsP[i]);
  float* outsD[3] = {QD, KD, VD};
  for (int i = 0; i < 3; ++i)
    gemm_proj_mma<<<dim3(64, 8), 256>>>(DRH, DRL, WHb + (size_t)(i + 3) * 262144,
                                        WLb + (size_t)(i + 3) * 262144, outsD[i]);

  // protein->drug: Lq=512, Lk=256
  gemm_logits<<<dim3(4, 4, 256), 128>>>(QP, KD, Sb, mpg, mdg, 512, 256);
  softmax_kernel<256><<<dim3(512, 32), 256>>>(Sb, mpg, out + OFF_APD, 512);
  gemm_av<<<dim3(4, 1, 256), 128>>>(Sb, VD, out + OFF_PROT, 512, 256);

  // drug->protein: Lq=256, Lk=512
  gemm_logits<<<dim3(2, 8, 256), 128>>>(QD, KP, Sb, mdg, mpg, 256, 512);
  softmax_kernel<512><<<dim3(256, 32), 256>>>(Sb, mdg, out + OFF_ADP, 256);
  gemm_av<<<dim3(2, 1, 256), 128>>>(Sb, VP, out + OFF_DRUG, 256, 512);

  (void)in_sizes; (void)n_in; (void)out_size;
}

// round 5
// speedup vs baseline: 1.6630x; 1.1587x over previous
#include <cuda_runtime.h>
#include <cuda_bf16.h>
#include <cstdint>

#define NB    32
#define LP    2048
#define LDRG  256
#define DD    512
#define GPNUM 512

typedef unsigned short u16;

// ======================= scratch (floats) =======================
//  S    0         (33554432)  fp32 logits / in-place alpha bf16 hi|lo
//  QPh 33554432  QPl 37748736  KPh 41943040  KPl 46137344
//  VPh 50331648  VPl 54525952
//  QDh 58720256  QDl 60817408  KDh 62914560  KDl 65011712
//  VDh 67108864  VDl 69206016
//  PGH 71303168  PGL 75497472  DRH 79691776  DRL 81788928
//  WH  83886080  WL  84672512
__device__ float g_scratch[85458944];
__device__ unsigned char g_masks[24576];
__device__ int g_flag;

__device__ __forceinline__ u16 bf16bits(float x) {
  __nv_bfloat16 h = __float2bfloat16_rn(x);
  return *reinterpret_cast<u16*>(&h);
}
__device__ __forceinline__ float bf16val(u16 b) {
  __nv_bfloat16 h = *reinterpret_cast<__nv_bfloat16*>(&b);
  return __bfloat162float(h);
}
// split v0,v1 into packed hi u32 and lo u32
__device__ __forceinline__ void split2(float v0, float v1, uint32_t& hi, uint32_t& lo) {
  u16 h0 = bf16bits(v0), h1 = bf16bits(v1);
  u16 l0 = bf16bits(v0 - bf16val(h0)), l1 = bf16bits(v1 - bf16val(h1));
  hi = (uint32_t)h0 | ((uint32_t)h1 << 16);
  lo = (uint32_t)l0 | ((uint32_t)l1 << 16);
}

// ======================= masks =======================
__device__ __forceinline__ bool read_mask(const void* p, int i, int f) {
  if (f == 0) return ((const unsigned char*)p)[i] != 0;
  if (f == 1) return ((const int*)p)[i] != 0;
  return ((const float*)p)[i] != 0.0f;
}
__global__ void detect_kernel(const unsigned char* __restrict__ p) {
  int big = 0, off = 0;
  for (int i = 0; i < 1024; ++i) {
    unsigned char c = p[i];
    big |= (c > 1) ? 1 : 0;
    off |= (c != 0 && (i & 3) != 0) ? 1 : 0;
  }
  g_flag = big ? 2 : (off ? 0 : 1);
}
__global__ void mask_kernel(const void* __restrict__ mp, const void* __restrict__ md,
                            float* __restrict__ outMP, float* __restrict__ outMD) {
  int f = g_flag;
  int idx = blockIdx.x * blockDim.x + threadIdx.x;
  if (idx < NB * GPNUM) {
    int b = idx / GPNUM, g = idx % GPNUM;
    int base = b * LP + g * 4;
    bool any = false;
#pragma unroll
    for (int r = 0; r < 4; ++r) any = any || read_mask(mp, base + r, f);
    g_masks[idx] = any ? 1 : 0;
    outMP[idx] = any ? 1.0f : 0.0f;
  } else {
    int j = idx - NB * GPNUM;
    if (j < NB * LDRG) {
      bool v = read_mask(md, j, f);
      g_masks[16384 + j] = v ? 1 : 0;
      outMD[j] = v ? 1.0f : 0.0f;
    }
  }
}

// ============== grouping + bf16 hi/lo split ==============
__global__ void group_bf16_kernel(const float* __restrict__ P,
                                  u16* __restrict__ H, u16* __restrict__ L) {
  int idx = blockIdx.x * 256 + threadIdx.x;
  int d = idx & 511;
  int g = (idx >> 9) & 511;
  int b = idx >> 18;
  const float* p = P + ((size_t)b * LP + (size_t)g * 4) * DD + d;
  float x = 0.25f * (p[0] + p[512] + p[1024] + p[1536]);
  u16 h = bf16bits(x);
  H[idx] = h;
  L[idx] = bf16bits(x - bf16val(h));
}
__global__ void cvt_bf16_kernel(const float* __restrict__ X, int n,
                                u16* __restrict__ H, u16* __restrict__ L) {
  int i = blockIdx.x * 256 + threadIdx.x;
  if (i >= n) return;
  float x = X[i];
  u16 h = bf16bits(x);
  H[i] = h;
  L[i] = bf16bits(x - bf16val(h));
}

// ======================= HMMA macro =======================
#define MMA_BF16(c, a, b)                                                      \
  asm volatile("mma.sync.aligned.m16n8k16.row.col.f32.bf16.bf16.f32 "          \
               "{%0,%1,%2,%3}, {%4,%5,%6,%7}, {%8,%9}, {%0,%1,%2,%3};"         \
               : "+f"((c)[0]), "+f"((c)[1]), "+f"((c)[2]), "+f"((c)[3])        \
               : "r"((a)[0]), "r"((a)[1]), "r"((a)[2]), "r"((a)[3]),           \
                 "r"((b)[0]), "r"((b)[1]))

// fragment loads from smem tiles As[.][40]/Bs[.][40] (row-major, k contiguous)
#define LOAD_A_FRAGS(ah, al, Ahs, Als, wm, g, kb)                              \
  _Pragma("unroll") for (int mi = 0; mi < 2; ++mi) {                           \
    int r0 = (wm) + mi * 16 + (g), r1 = r0 + 8;                                \
    ah[mi][0] = *(const uint32_t*)&Ahs[r0][kb];                                \
    ah[mi][1] = *(const uint32_t*)&Ahs[r1][kb];                                \
    ah[mi][2] = *(const uint32_t*)&Ahs[r0][(kb) + 8];                          \
    ah[mi][3] = *(const uint32_t*)&Ahs[r1][(kb) + 8];                          \
    al[mi][0] = *(const uint32_t*)&Als[r0][kb];                                \
    al[mi][1] = *(const uint32_t*)&Als[r1][kb];                                \
    al[mi][2] = *(const uint32_t*)&Als[r0][(kb) + 8];                          \
    al[mi][3] = *(const uint32_t*)&Als[r1][(kb) + 8];                          \
  }

// ====== bf16x3 projection: C[M,512] = A[M,512] @ W[512,512]^T, bf16 hi/lo out ======
__global__ __launch_bounds__(256) void gemm_proj_mma(
    const u16* __restrict__ Ah, const u16* __restrict__ Al,
    const u16* __restrict__ Wh, const u16* __restrict__ Wl,
    u16* __restrict__ Ch, u16* __restrict__ Cl) {
  __shared__ __align__(16) u16 Ahs[128][40];
  __shared__ __align__(16) u16 Als[128][40];
  __shared__ __align__(16) u16 Bhs[64][40];
  __shared__ __align__(16) u16 Bls[64][40];

  const int tid = threadIdx.x;
  const int w = tid >> 5, lane = tid & 31;
  const int g = lane >> 2, t4 = lane & 3;
  const int wm = (w >> 1) * 32, wn = (w & 1) * 32;
  const int mBase = blockIdx.x * 128;
  const int nBase = blockIdx.y * 64;

  float acc[2][4][4];
#pragma unroll
  for (int mi = 0; mi < 2; ++mi)
#pragma unroll
    for (int j = 0; j < 4; ++j)
#pragma unroll
      for (int q = 0; q < 4; ++q) acc[mi][j][q] = 0.0f;

  for (int k0 = 0; k0 < 512; k0 += 32) {
#pragma unroll
    for (int u = tid; u < 512; u += 256) {
      int row = u >> 2, seg = u & 3;
      size_t ga = (size_t)(mBase + row) * 512 + k0 + seg * 8;
      *(uint4*)&Ahs[row][seg * 8] = *(const uint4*)(Ah + ga);
      *(uint4*)&Als[row][seg * 8] = *(const uint4*)(Al + ga);
    }
    if (tid < 256) {
      int row = tid >> 2, seg = tid & 3;
      size_t ga = (size_t)(nBase + row) * 512 + k0 + seg * 8;
      *(uint4*)&Bhs[row][seg * 8] = *(const uint4*)(Wh + ga);
      *(uint4*)&Bls[row][seg * 8] = *(const uint4*)(Wl + ga);
    }
    __syncthreads();
#pragma unroll
    for (int kk = 0; kk < 32; kk += 16) {
      const int kb = kk + t4 * 2;
      uint32_t ah[2][4], al[2][4];
      LOAD_A_FRAGS(ah, al, Ahs, Als, wm, g, kb);
      uint32_t bh[4][2], bl[4][2];
#pragma unroll
      for (int j = 0; j < 4; ++j) {
        int n = wn + j * 8 + g;
        bh[j][0] = *(const uint32_t*)&Bhs[n][kb];
        bh[j][1] = *(const uint32_t*)&Bhs[n][kb + 8];
        bl[j][0] = *(const uint32_t*)&Bls[n][kb];
        bl[j][1] = *(const uint32_t*)&Bls[n][kb + 8];
      }
#pragma unroll
      for (int mi = 0; mi < 2; ++mi)
#pragma unroll
        for (int j = 0; j < 4; ++j) {
          MMA_BF16(acc[mi][j], ah[mi], bh[j]);
          MMA_BF16(acc[mi][j], ah[mi], bl[j]);
          MMA_BF16(acc[mi][j], al[mi], bh[j]);
        }
    }
    __syncthreads();
  }

#pragma unroll
  for (int mi = 0; mi < 2; ++mi) {
    int row = mBase + wm + mi * 16 + g;
#pragma unroll
    for (int j = 0; j < 4; ++j) {
      int col = nBase + wn + j * 8 + t4 * 2;
      uint32_t hi, lo;
      split2(acc[mi][j][0], acc[mi][j][1], hi, lo);
      *(uint32_t*)(Ch + (size_t)row * 512 + col) = hi;
      *(uint32_t*)(Cl + (size_t)row * 512 + col) = lo;
      split2(acc[mi][j][2], acc[mi][j][3], hi, lo);
      *(uint32_t*)(Ch + (size_t)(row + 8) * 512 + col) = hi;
      *(uint32_t*)(Cl + (size_t)(row + 8) * 512 + col) = lo;
    }
  }
}

// ====== bf16x3 logits: S[b,h,l,k] = Q.K^T over dh=64, masked fp32 out ======
__global__ __launch_bounds__(256) void gemm_logits_mma(
    const u16* __restrict__ Qh, const u16* __restrict__ Ql,
    const u16* __restrict__ Kh, const u16* __restrict__ Kl,
    float* __restrict__ S,
    const unsigned char* __restrict__ mq, const unsigned char* __restrict__ mk,
    int Lq, int Lk) {
  __shared__ __align__(16) u16 Ahs[128][40];
  __shared__ __align__(16) u16 Als[128][40];
  __shared__ __align__(16) u16 Bhs[64][40];
  __shared__ __align__(16) u16 Bls[64][40];

  const int tid = threadIdx.x;
  const int w = tid >> 5, lane = tid & 31;
  const int g = lane >> 2, t4 = lane & 3;
  const int wm = (w >> 1) * 32, wn = (w & 1) * 32;
  const int mBase = blockIdx.x * 128;
  const int nBase = blockIdx.y * 64;
  const int z = blockIdx.z;
  const int b = z >> 3, h = z & 7;
  const u16* Ahg = Qh + (size_t)b * Lq * 512 + h * 64;
  const u16* Alg = Ql + (size_t)b * Lq * 512 + h * 64;
  const u16* Bhg = Kh + (size_t)b * Lk * 512 + h * 64;
  const u16* Blg = Kl + (size_t)b * Lk * 512 + h * 64;
  float* C = S + (size_t)z * Lq * Lk;
  const unsigned char* mqb = mq + b * Lq;
  const unsigned char* mkb = mk + b * Lk;

  float acc[2][4][4];
#pragma unroll
  for (int mi = 0; mi < 2; ++mi)
#pragma unroll
    for (int j = 0; j < 4; ++j)
#pragma unroll
      for (int q = 0; q < 4; ++q) acc[mi][j][q] = 0.0f;

#pragma unroll
  for (int k0 = 0; k0 < 64; k0 += 32) {
#pragma unroll
    for (int u = tid; u < 512; u += 256) {
      int row = u >> 2, seg = u & 3;
      size_t ga = (size_t)(mBase + row) * 512 + k0 + seg * 8;
      *(uint4*)&Ahs[row][seg * 8] = *(const uint4*)(Ahg + ga);
      *(uint4*)&Als[row][seg * 8] = *(const uint4*)(Alg + ga);
    }
    if (tid < 256) {
      int row = tid >> 2, seg = tid & 3;
      size_t ga = (size_t)(nBase + row) * 512 + k0 + seg * 8;
      *(uint4*)&Bhs[row][seg * 8] = *(const uint4*)(Bhg + ga);
      *(uint4*)&Bls[row][seg * 8] = *(const uint4*)(Blg + ga);
    }
    __syncthreads();
#pragma unroll
    for (int kk = 0; kk < 32; kk += 16) {
      const int kb = kk + t4 * 2;
      uint32_t ah[2][4], al[2][4];
      LOAD_A_FRAGS(ah, al, Ahs, Als, wm, g, kb);
      uint32_t bh[4][2], bl[4][2];
#pragma unroll
      for (int j = 0; j < 4; ++j) {
        int n = wn + j * 8 + g;
        bh[j][0] = *(const uint32_t*)&Bhs[n][kb];
        bh[j][1] = *(const uint32_t*)&Bhs[n][kb + 8];
        bl[j][0] = *(const uint32_t*)&Bls[n][kb];
        bl[j][1] = *(const uint32_t*)&Bls[n][kb + 8];
      }
#pragma unroll
      for (int mi = 0; mi < 2; ++mi)
#pragma unroll
        for (int j = 0; j < 4; ++j) {
          MMA_BF16(acc[mi][j], ah[mi], bh[j]);
          MMA_BF16(acc[mi][j], ah[mi], bl[j]);
          MMA_BF16(acc[mi][j], al[mi], bh[j]);
        }
    }
    __syncthreads();
  }

#pragma unroll
  for (int mi = 0; mi < 2; ++mi) {
    int row = mBase + wm + mi * 16 + g;
    float p0 = mqb[row] ? 0.0f : 1.0e6f;
    float p1 = mqb[row + 8] ? 0.0f : 1.0e6f;
#pragma unroll
    for (int j = 0; j < 4; ++j) {
      int col = nBase + wn + j * 8 + t4 * 2;
      float c0 = mkb[col] ? 0.0f : 1.0e6f;
      float c1 = mkb[col + 1] ? 0.0f : 1.0e6f;
      *(float2*)(C + (size_t)row * Lk + col) =
          make_float2(acc[mi][j][0] - fmaxf(p0, c0), acc[mi][j][1] - fmaxf(p0, c1));
      *(float2*)(C + (size_t)(row + 8) * Lk + col) =
          make_float2(acc[mi][j][2] - fmaxf(p1, c0), acc[mi][j][3] - fmaxf(p1, c1));
    }
  }
}

// ====== bf16x3 AV: Out[b,l,h*64+n] = sum_k alpha[b,h,l,k] V[b,k,h*64+n] ======
// alpha stored in-place in S rows as bf16 hi|lo halves.
__global__ __launch_bounds__(256) void gemm_av_mma(
    const float* __restrict__ S, const u16* __restrict__ Vh, const u16* __restrict__ Vl,
    float* __restrict__ Out, int Lq, int Lk) {
  __shared__ __align__(16) u16 Ahs[128][40];
  __shared__ __align__(16) u16 Als[128][40];
  __shared__ __align__(16) u16 Bhs[64][42];
  __shared__ __align__(16) u16 Bls[64][42];

  const int tid = threadIdx.x;
  const int w = tid >> 5, lane = tid & 31;
  const int g = lane >> 2, t4 = lane & 3;
  const int wm = (w >> 1) * 32, wn = (w & 1) * 32;
  const int mBase = blockIdx.x * 128;
  const int z = blockIdx.z;
  const int b = z >> 3, h = z & 7;
  const u16* Abase = (const u16*)(S + (size_t)z * Lq * Lk);  // row: l*2*Lk; hi at +k, lo at +Lk+k
  const size_t vbase = (size_t)b * Lk * 512 + h * 64;
  float* C = Out + (size_t)b * Lq * 512 + h * 64;

  float acc[2][4][4];
#pragma unroll
  for (int mi = 0; mi < 2; ++mi)
#pragma unroll
    for (int j = 0; j < 4; ++j)
#pragma unroll
      for (int q = 0; q < 4; ++q) acc[mi][j][q] = 0.0f;

  for (int k0 = 0; k0 < Lk; k0 += 32) {
    // alpha tiles: 128 rows x 32 k (hi & lo)
#pragma unroll
    for (int u = tid; u < 512; u += 256) {
      int row = u >> 2, seg = u & 3;
      const u16* ar = Abase + (size_t)(mBase + row) * 2 * Lk + k0 + seg * 8;
      *(uint4*)&Ahs[row][seg * 8] = *(const uint4*)ar;
      *(uint4*)&Als[row][seg * 8] = *(const uint4*)(ar + Lk);
    }
    // V tiles transposed: Bs[n][k] from V[(k0+k)][h*64+n]; 32k x 64n
#pragma unroll
    for (int u = tid; u < 1024; u += 256) {
      int k = u >> 5, np = (u & 31) * 2;
      size_t ga = vbase + (size_t)(k0 + k) * 512 + np;
      uint32_t vh = *(const uint32_t*)(Vh + ga);
      uint32_t vl = *(const uint32_t*)(Vl + ga);
      Bhs[np][k] = (u16)(vh & 0xffffu);
      Bhs[np + 1][k] = (u16)(vh >> 16);
      Bls[np][k] = (u16)(vl & 0xffffu);
      Bls[np + 1][k] = (u16)(vl >> 16);
    }
    __syncthreads();
#pragma unroll
    for (int kk = 0; kk < 32; kk += 16) {
      const int kb = kk + t4 * 2;
      uint32_t ah[2][4], al[2][4];
      LOAD_A_FRAGS(ah, al, Ahs, Als, wm, g, kb);
      uint32_t bh[4][2], bl[4][2];
#pragma unroll
      for (int j = 0; j < 4; ++j) {
        int n = wn + j * 8 + g;
        bh[j][0] = *(const uint32_t*)&Bhs[n][kb];
        bh[j][1] = *(const uint32_t*)&Bhs[n][kb + 8];
        bl[j][0] = *(const uint32_t*)&Bls[n][kb];
        bl[j][1] = *(const uint32_t*)&Bls[n][kb + 8];
      }
#pragma unroll
      for (int mi = 0; mi < 2; ++mi)
#pragma unroll
        for (int j = 0; j < 4; ++j) {
          MMA_BF16(acc[mi][j], ah[mi], bh[j]);
          MMA_BF16(acc[mi][j], ah[mi], bl[j]);
          MMA_BF16(acc[mi][j], al[mi], bh[j]);
        }
    }
    __syncthreads();
  }

#pragma unroll
  for (int mi = 0; mi < 2; ++mi) {
    int row = mBase + wm + mi * 16 + g;
#pragma unroll
    for (int j = 0; j < 4; ++j) {
      int col = wn + j * 8 + t4 * 2;
      *(float2*)(C + (size_t)row * 512 + col) = make_float2(acc[mi][j][0], acc[mi][j][1]);
      *(float2*)(C + (size_t)(row + 8) * 512 + col) = make_float2(acc[mi][j][2], acc[mi][j][3]);
    }
  }
}

// ---------------- softmax: fp32 in S -> alpha fp32 out + bf16 hi/lo in-place ----------------
template <int LK>
__global__ __launch_bounds__(256) void softmax_kernel(
    float* __restrict__ S, const unsigned char* __restrict__ mq,
    float* __restrict__ alphaOut, int Lq) {
  __shared__ float sbuf[8][LK + 1];
  const int l = blockIdx.x, b = blockIdx.y;
  const int tid = threadIdx.x, w = tid >> 5, lane = tid & 31;
  const size_t abase = ((size_t)b * Lq + l) * (size_t)(LK * 8);

  if (!mq[b * Lq + l]) {
    for (int idx = tid; idx < LK * 8; idx += 256) alphaOut[abase + idx] = 0.0f;
#pragma unroll
    for (int h = 0; h < 8; ++h) {
      float* srow = S + ((size_t)(b * 8 + h) * Lq + l) * LK;
      for (int k = tid; k < LK; k += 256) srow[k] = 0.0f;  // zeroes hi|lo bf16 halves too
    }
    return;
  }

  float* srow = S + ((size_t)(b * 8 + w) * Lq + l) * LK;
  const int nit = LK / 32;
  float v[LK / 32];
  float mx = -3.0e38f;
#pragma unroll
  for (int i = 0; i < nit; ++i) { v[i] = srow[lane + 32 * i]; mx = fmaxf(mx, v[i]); }
#pragma unroll
  for (int o = 16; o > 0; o >>= 1) mx = fmaxf(mx, __shfl_xor_sync(0xffffffffu, mx, o));
  float sum = 0.0f;
#pragma unroll
  for (int i = 0; i < nit; ++i) { float e = expf(v[i] - mx); v[i] = e; sum += e; }
#pragma unroll
  for (int o = 16; o > 0; o >>= 1) sum += __shfl_xor_sync(0xffffffffu, sum, o);
  float inv = 1.0f / sum;
  u16* arow = (u16*)srow;
#pragma unroll
  for (int i = 0; i < nit; ++i) {
    float a = v[i] * inv;
    sbuf[w][lane + 32 * i] = a;
    u16 hb = bf16bits(a);
    arow[lane + 32 * i] = hb;                     // hi half
    arow[LK + lane + 32 * i] = bf16bits(a - bf16val(hb));  // lo half
  }
  __syncthreads();
#pragma unroll 4
  for (int idx = tid; idx < LK * 8; idx += 256) {
    int k = idx >> 3, h = idx & 7;
    alphaOut[abase + idx] = sbuf[h][k];
  }
}

// ---------------- launch ----------------
extern "C" void kernel_launch(void* const* d_in, const int* in_sizes, int n_in,
                              void* d_out, int out_size) {
  const float* protein = (const float*)d_in[0];
  const float* drug    = (const float*)d_in[1];
  const void*  mpraw   = d_in[2];
  const void*  mdraw   = d_in[3];
  const float* W[6] = {(const float*)d_in[4], (const float*)d_in[5], (const float*)d_in[6],
                       (const float*)d_in[7], (const float*)d_in[8], (const float*)d_in[9]};
  float* out = (float*)d_out;

  float* sc = nullptr;
  cudaGetSymbolAddress((void**)&sc, g_scratch);
  unsigned char* mg = nullptr;
  cudaGetSymbolAddress((void**)&mg, g_masks);

  float* Sb = sc;
  u16* QPh = (u16*)(sc + 33554432); u16* QPl = (u16*)(sc + 37748736);
  u16* KPh = (u16*)(sc + 41943040); u16* KPl = (u16*)(sc + 46137344);
  u16* VPh = (u16*)(sc + 50331648); u16* VPl = (u16*)(sc + 54525952);
  u16* QDh = (u16*)(sc + 58720256); u16* QDl = (u16*)(sc + 60817408);
  u16* KDh = (u16*)(sc + 62914560); u16* KDl = (u16*)(sc + 65011712);
  u16* VDh = (u16*)(sc + 67108864); u16* VDl = (u16*)(sc + 69206016);
  u16* PGH = (u16*)(sc + 71303168); u16* PGL = (u16*)(sc + 75497472);
  u16* DRH = (u16*)(sc + 79691776); u16* DRL = (u16*)(sc + 81788928);
  u16* WHb = (u16*)(sc + 83886080); u16* WLb = (u16*)(sc + 84672512);
  unsigned char* mpg = mg;
  unsigned char* mdg = mg + 16384;

  const size_t OFF_PROT = 0;
  const size_t OFF_DRUG = 8388608;
  const size_t OFF_MP   = 12582912;
  const size_t OFF_MD   = 12599296;
  const size_t OFF_APD  = 12607488;
  const size_t OFF_ADP  = 46161920;

  detect_kernel<<<1, 1>>>((const unsigned char*)mpraw);
  mask_kernel<<<96, 256>>>(mpraw, mdraw, out + OFF_MP, out + OFF_MD);
  group_bf16_kernel<<<32768, 256>>>(protein, PGH, PGL);
  cvt_bf16_kernel<<<16384, 256>>>(drug, 4194304, DRH, DRL);
  for (int i = 0; i < 6; ++i)
    cvt_bf16_kernel<<<1024, 256>>>(W[i], 262144, WHb + (size_t)i * 262144,
                                   WLb + (size_t)i * 262144);

  // projections -> bf16 hi/lo
  u16* PH[3] = {QPh, KPh, VPh}; u16* PL[3] = {QPl, KPl, VPl};
  for (int i = 0; i < 3; ++i)
    gemm_proj_mma<<<dim3(128, 8), 256>>>(PGH, PGL, WHb + (size_t)i * 262144,
                                         WLb + (size_t)i * 262144, PH[i], PL[i]);
  u16* DH[3] = {QDh, KDh, VDh}; u16* DL[3] = {QDl, KDl, VDl};
  for (int i = 0; i < 3; ++i)
    gemm_proj_mma<<<dim3(64, 8), 256>>>(DRH, DRL, WHb + (size_t)(i + 3) * 262144,
                                        WLb + (size_t)(i + 3) * 262144, DH[i], DL[i]);

  // protein->drug: Lq=512, Lk=256
  gemm_logits_mma<<<dim3(4, 4, 256), 256>>>(QPh, QPl, KDh, KDl, Sb, mpg, mdg, 512, 256);
  softmax_kernel<256><<<dim3(512, 32), 256>>>(Sb, mpg, out + OFF_APD, 512);
  gemm_av_mma<<<dim3(4, 1, 256), 256>>>(Sb, VDh, VDl, out + OFF_PROT, 512, 256);

  // drug->protein: Lq=256, Lk=512
  gemm_logits_mma<<<dim3(2, 8, 256), 256>>>(QDh, QDl, KPh, KPl, Sb, mdg, mpg, 256, 512);
  softmax_kernel<512><<<dim3(256, 32), 256>>>(Sb, mdg, out + OFF_ADP, 256);
  gemm_av_mma<<<dim3(2, 1, 256), 256>>>(Sb, VPh, VPl, out + OFF_DRUG, 256, 512);

  (void)in_sizes; (void)n_in; (void)out_size;
}